// round 1
// baseline (speedup 1.0000x reference)
#include <cuda_runtime.h>
#include <cstdint>

#define NN_DIM 5000
#define NF 128
#define NOUT 16
#define NPAD 5120
#define BT 128
#define TPAD 132
#define NTHREADS 256

// Scratch: S1 = feature@W3 (group 0), S2 = feature@W1 (group 1).
// Padded to 5120 rows so edge-tile SMEM staging never reads out of bounds
// (pad rows are zero-initialized .bss and always multiplied by zero-filled T).
__device__ float g_S[2][NPAD][NOUT];

// ---------- packed f32x2 helpers (ptxas never emits FFMA2 from C++) ----------
__device__ __forceinline__ void fma2(unsigned long long &d, unsigned long long a,
                                     unsigned long long b) {
    asm("fma.rn.f32x2 %0, %1, %2, %0;" : "+l"(d) : "l"(a), "l"(b));
}
__device__ __forceinline__ unsigned long long pack2(float x) {
    unsigned long long r;
    asm("mov.b64 %0, {%1, %1};" : "=l"(r) : "f"(x));
    return r;
}
__device__ __forceinline__ float2 unpack2(unsigned long long v) {
    float2 f;
    asm("mov.b64 {%0, %1}, %2;" : "=f"(f.x), "=f"(f.y) : "l"(v));
    return f;
}

// ---------------- prep: S1/S2 = feature @ W, and bias-init out ----------------
__global__ void fame_prep(const float* __restrict__ feature,
                          const float* __restrict__ W3, const float* __restrict__ b3,
                          const float* __restrict__ W1, const float* __restrict__ b1,
                          float* __restrict__ out) {
    __shared__ float fsm[NF];
    const int row = blockIdx.x;
    const int t = threadIdx.x;
    fsm[t] = feature[row * NF + t];
    __syncthreads();
    if (t < 32) {
        const int g = t >> 4;
        const int c = t & 15;
        const float* __restrict__ W = g ? W1 : W3;
        float s = 0.f;
#pragma unroll 16
        for (int k = 0; k < NF; k++) s += fsm[k] * W[k * NOUT + c];
        g_S[g][row][c] = s;
    } else if (t < 64) {
        const int c = t - 32;
        out[row * 32 + c] = (c < 16) ? b3[c] : b1[c - 16];
    }
}

// --------------- per-group mainloop (inlined twice for static acc) ---------------
__device__ __forceinline__ void do_group(
    const float* __restrict__ mats, int nmat, const float* __restrict__ wv,
    float* __restrict__ Tsm, const float* __restrict__ Sj, const float* __restrict__ Si,
    int i0, int j0, int t, bool fast, unsigned long long acc[8])
{
    for (int m = 0; m < nmat; m++) {
        const float* __restrict__ M = mats + (size_t)m * (size_t)NN_DIM * (size_t)NN_DIM;
        const float w = wv[m];

        __syncthreads();  // previous tile fully consumed (also covers S staging)

        // ---- stage 128x128 tile, pre-scaled by w ----
        if (fast) {
#pragma unroll
            for (int q = 0; q < 16; q++) {
                const int idx = t + NTHREADS * q;
                const int row = idx >> 5;
                const int c4 = idx & 31;
                const float4 v = *(const float4*)(M + (size_t)(i0 + row) * NN_DIM + (j0 + c4 * 4));
                float4 s;
                s.x = v.x * w; s.y = v.y * w; s.z = v.z * w; s.w = v.w * w;
                *(float4*)(Tsm + row * TPAD + c4 * 4) = s;
            }
        } else {
#pragma unroll
            for (int q = 0; q < 16; q++) {
                const int idx = t + NTHREADS * q;
                const int row = idx >> 5;
                const int c4 = idx & 31;
                const int gi = i0 + row;
                const int gj = j0 + c4 * 4;
                float4 s = make_float4(0.f, 0.f, 0.f, 0.f);
                if (gi < NN_DIM) {
                    const float* __restrict__ p = M + (size_t)gi * NN_DIM + gj;
                    if (gj + 3 < NN_DIM) {
                        const float4 v = *(const float4*)p;
                        s.x = v.x * w; s.y = v.y * w; s.z = v.z * w; s.w = v.w * w;
                    } else {
                        if (gj + 0 < NN_DIM) s.x = p[0] * w;
                        if (gj + 1 < NN_DIM) s.y = p[1] * w;
                        if (gj + 2 < NN_DIM) s.z = p[2] * w;
                    }
                }
                *(float4*)(Tsm + row * TPAD + c4 * 4) = s;
            }
        }
        __syncthreads();

        if (t < BT) {
            // GEMM1: out rows i — acc[i,:] += sum_j T[i,j] * Sj[j,:]
            const int r = t;
            const float* __restrict__ Trow = Tsm + r * TPAD;
#pragma unroll 2
            for (int j4 = 0; j4 < 32; j4++) {
                const float4 tv = *(const float4*)(Trow + j4 * 4);
#pragma unroll
                for (int k = 0; k < 4; k++) {
                    const float mv = (k == 0) ? tv.x : (k == 1) ? tv.y : (k == 2) ? tv.z : tv.w;
                    const unsigned long long m2 = pack2(mv);
                    const ulonglong2* __restrict__ Sp =
                        (const ulonglong2*)(Sj + (j4 * 4 + k) * NOUT);
                    const ulonglong2 p0 = Sp[0], p1 = Sp[1], p2 = Sp[2], p3 = Sp[3];
                    fma2(acc[0], m2, p0.x); fma2(acc[1], m2, p0.y);
                    fma2(acc[2], m2, p1.x); fma2(acc[3], m2, p1.y);
                    fma2(acc[4], m2, p2.x); fma2(acc[5], m2, p2.y);
                    fma2(acc[6], m2, p3.x); fma2(acc[7], m2, p3.y);
                }
            }
        } else {
            // GEMM2: out rows j (transpose part) — acc[j,:] += sum_i T[i,j] * Si[i,:]
            const int tt = t - BT;
#pragma unroll 4
            for (int i = 0; i < BT; i++) {
                const float mv = Tsm[i * TPAD + tt];
                const unsigned long long m2 = pack2(mv);
                const ulonglong2* __restrict__ Sp = (const ulonglong2*)(Si + i * NOUT);
                const ulonglong2 p0 = Sp[0], p1 = Sp[1], p2 = Sp[2], p3 = Sp[3];
                fma2(acc[0], m2, p0.x); fma2(acc[1], m2, p0.y);
                fma2(acc[2], m2, p1.x); fma2(acc[3], m2, p1.y);
                fma2(acc[4], m2, p2.x); fma2(acc[5], m2, p2.y);
                fma2(acc[6], m2, p3.x); fma2(acc[7], m2, p3.y);
            }
        }
    }
}

__global__ __launch_bounds__(NTHREADS, 2)
void fame_main(const float* __restrict__ A, const float* __restrict__ At,
               const float* __restrict__ wA, const float* __restrict__ wB,
               float* __restrict__ out)
{
    extern __shared__ float smem[];
    float* Tsm = smem;                    // [128][132]
    float* Sj = Tsm + BT * TPAD;          // [2][128][16]
    float* Si = Sj + 2 * BT * NOUT;       // [2][128][16]

    const int t = threadIdx.x;
    const int bi = blockIdx.y, bj = blockIdx.x;
    const int i0 = bi * BT, j0 = bj * BT;

    // stage S tiles for both groups (rows j-block for GEMM1, rows i-block for GEMM2)
    for (int idx = t; idx < 2 * BT * NOUT; idx += NTHREADS) {
        const int g = idx / (BT * NOUT);
        const int rem = idx - g * (BT * NOUT);
        const int r = rem >> 4;
        const int c = rem & 15;
        Sj[idx] = g_S[g][j0 + r][c];
        Si[idx] = g_S[g][i0 + r][c];
    }

    const bool fast = (i0 + BT <= NN_DIM) && (j0 + BT <= NN_DIM);

    unsigned long long accA[8], accB[8];
#pragma unroll
    for (int q = 0; q < 8; q++) { accA[q] = 0ull; accB[q] = 0ull; }

    do_group(A, 3, wA, Tsm, Sj, Si, i0, j0, t, fast, accA);
    do_group(At, 9, wB, Tsm, Sj + BT * NOUT, Si + BT * NOUT, i0, j0, t, fast, accB);

    // single atomic flush per thread
    const int grow = (t < BT) ? (i0 + t) : (j0 + (t - BT));
    if (grow < NN_DIM) {
        float* __restrict__ o = out + grow * 32;
#pragma unroll
        for (int q = 0; q < 8; q++) {
            const float2 a = unpack2(accA[q]);
            atomicAdd(o + 2 * q + 0, a.x);
            atomicAdd(o + 2 * q + 1, a.y);
            const float2 b = unpack2(accB[q]);
            atomicAdd(o + 16 + 2 * q + 0, b.x);
            atomicAdd(o + 16 + 2 * q + 1, b.y);
        }
    }
}

extern "C" void kernel_launch(void* const* d_in, const int* in_sizes, int n_in,
                              void* d_out, int out_size) {
    const float* feature = (const float*)d_in[0];  // [5000,128]
    const float* A       = (const float*)d_in[1];  // [3,5000,5000]
    const float* At      = (const float*)d_in[2];  // [9,5000,5000]
    const float* wb2     = (const float*)d_in[3];  // [3,1]
    const float* wb      = (const float*)d_in[4];  // [9,1]
    const float* W3      = (const float*)d_in[5];  // [128,16]
    const float* b3      = (const float*)d_in[6];  // [16]
    const float* W1      = (const float*)d_in[7];  // [128,16]
    const float* b1      = (const float*)d_in[8];  // [16]
    float* out = (float*)d_out;                    // [5000,32]

    // 1) S1/S2 + bias-init of out (out is poisoned 0xAA before timing)
    fame_prep<<<NN_DIM, 128>>>(feature, W3, b3, W1, b1, out);

    // 2) fused merged-adjacency x support, both groups, single pass over A/A_t
    const int smem_bytes = (BT * TPAD + 4 * BT * NOUT) * (int)sizeof(float);
    cudaFuncSetAttribute(fame_main, cudaFuncAttributeMaxDynamicSharedMemorySize, smem_bytes);
    dim3 grid((NN_DIM + BT - 1) / BT, (NN_DIM + BT - 1) / BT);
    fame_main<<<grid, NTHREADS, smem_bytes>>>(A, At, wb2, wb, out);
}

// round 2
// speedup vs baseline: 1.0022x; 1.0022x over previous
#include <cuda_runtime.h>
#include <cstdint>

#define NN_DIM 5000
#define NF 128
#define NOUT 16
#define NPAD 5120
#define BT 128
#define TPAD 132
#define NTHREADS 256

// Scratch: S1 = feature@W3 (group 0), S2 = feature@W1 (group 1).
// Padded to 5120 rows so edge-tile SMEM staging never reads out of bounds
// (pad rows are zero-initialized .bss and always multiplied by zero-filled T).
__device__ float g_S[2][NPAD][NOUT];

// ---------- packed f32x2 helpers (ptxas never emits FFMA2 from C++) ----------
__device__ __forceinline__ void fma2(unsigned long long &d, unsigned long long a,
                                     unsigned long long b) {
    asm("fma.rn.f32x2 %0, %1, %2, %0;" : "+l"(d) : "l"(a), "l"(b));
}
__device__ __forceinline__ unsigned long long pack2(float x) {
    unsigned long long r;
    asm("mov.b64 %0, {%1, %1};" : "=l"(r) : "f"(x));
    return r;
}
__device__ __forceinline__ float2 unpack2(unsigned long long v) {
    float2 f;
    asm("mov.b64 {%0, %1}, %2;" : "=f"(f.x), "=f"(f.y) : "l"(v));
    return f;
}

// ---------------- prep: S1/S2 = feature @ W, and bias-init out ----------------
__global__ void fame_prep(const float* __restrict__ feature,
                          const float* __restrict__ W3, const float* __restrict__ b3,
                          const float* __restrict__ W1, const float* __restrict__ b1,
                          float* __restrict__ out) {
    __shared__ float fsm[NF];
    const int row = blockIdx.x;
    const int t = threadIdx.x;
    fsm[t] = feature[row * NF + t];
    __syncthreads();
    if (t < 32) {
        const int g = t >> 4;
        const int c = t & 15;
        const float* __restrict__ W = g ? W1 : W3;
        float s = 0.f;
#pragma unroll 16
        for (int k = 0; k < NF; k++) s += fsm[k] * W[k * NOUT + c];
        g_S[g][row][c] = s;
    } else if (t < 64) {
        const int c = t - 32;
        out[row * 32 + c] = (c < 16) ? b3[c] : b1[c - 16];
    }
}

// --------------- per-group mainloop (inlined twice for static acc) ---------------
__device__ __forceinline__ void do_group(
    const float* __restrict__ mats, int nmat, const float* __restrict__ wv,
    float* __restrict__ Tsm, const float* __restrict__ Sj, const float* __restrict__ Si,
    int i0, int j0, int t, bool fast, unsigned long long acc[8])
{
    for (int m = 0; m < nmat; m++) {
        const float* __restrict__ M = mats + (size_t)m * (size_t)NN_DIM * (size_t)NN_DIM;
        const float w = wv[m];

        __syncthreads();  // previous tile fully consumed (also covers S staging)

        // ---- stage 128x128 tile, pre-scaled by w ----
        if (fast) {
#pragma unroll
            for (int q = 0; q < 16; q++) {
                const int idx = t + NTHREADS * q;
                const int row = idx >> 5;
                const int c4 = idx & 31;
                const float4 v = *(const float4*)(M + (size_t)(i0 + row) * NN_DIM + (j0 + c4 * 4));
                float4 s;
                s.x = v.x * w; s.y = v.y * w; s.z = v.z * w; s.w = v.w * w;
                *(float4*)(Tsm + row * TPAD + c4 * 4) = s;
            }
        } else {
#pragma unroll
            for (int q = 0; q < 16; q++) {
                const int idx = t + NTHREADS * q;
                const int row = idx >> 5;
                const int c4 = idx & 31;
                const int gi = i0 + row;
                const int gj = j0 + c4 * 4;
                float4 s = make_float4(0.f, 0.f, 0.f, 0.f);
                if (gi < NN_DIM) {
                    const float* __restrict__ p = M + (size_t)gi * NN_DIM + gj;
                    if (gj + 3 < NN_DIM) {
                        const float4 v = *(const float4*)p;
                        s.x = v.x * w; s.y = v.y * w; s.z = v.z * w; s.w = v.w * w;
                    } else {
                        if (gj + 0 < NN_DIM) s.x = p[0] * w;
                        if (gj + 1 < NN_DIM) s.y = p[1] * w;
                        if (gj + 2 < NN_DIM) s.z = p[2] * w;
                    }
                }
                *(float4*)(Tsm + row * TPAD + c4 * 4) = s;
            }
        }
        __syncthreads();

        if (t < BT) {
            // GEMM1: out rows i — acc[i,:] += sum_j T[i,j] * Sj[j,:]
            const int r = t;
            const float* __restrict__ Trow = Tsm + r * TPAD;
#pragma unroll 2
            for (int j4 = 0; j4 < 32; j4++) {
                const float4 tv = *(const float4*)(Trow + j4 * 4);
#pragma unroll
                for (int k = 0; k < 4; k++) {
                    const float mv = (k == 0) ? tv.x : (k == 1) ? tv.y : (k == 2) ? tv.z : tv.w;
                    const unsigned long long m2 = pack2(mv);
                    const ulonglong2* __restrict__ Sp =
                        (const ulonglong2*)(Sj + (j4 * 4 + k) * NOUT);
                    const ulonglong2 p0 = Sp[0], p1 = Sp[1], p2 = Sp[2], p3 = Sp[3];
                    fma2(acc[0], m2, p0.x); fma2(acc[1], m2, p0.y);
                    fma2(acc[2], m2, p1.x); fma2(acc[3], m2, p1.y);
                    fma2(acc[4], m2, p2.x); fma2(acc[5], m2, p2.y);
                    fma2(acc[6], m2, p3.x); fma2(acc[7], m2, p3.y);
                }
            }
        } else {
            // GEMM2: out rows j (transpose part) — acc[j,:] += sum_i T[i,j] * Si[i,:]
            const int tt = t - BT;
#pragma unroll 4
            for (int i = 0; i < BT; i++) {
                const float mv = Tsm[i * TPAD + tt];
                const unsigned long long m2 = pack2(mv);
                const ulonglong2* __restrict__ Sp = (const ulonglong2*)(Si + i * NOUT);
                const ulonglong2 p0 = Sp[0], p1 = Sp[1], p2 = Sp[2], p3 = Sp[3];
                fma2(acc[0], m2, p0.x); fma2(acc[1], m2, p0.y);
                fma2(acc[2], m2, p1.x); fma2(acc[3], m2, p1.y);
                fma2(acc[4], m2, p2.x); fma2(acc[5], m2, p2.y);
                fma2(acc[6], m2, p3.x); fma2(acc[7], m2, p3.y);
            }
        }
    }
}

__global__ __launch_bounds__(NTHREADS, 2)
void fame_main(const float* __restrict__ A, const float* __restrict__ At,
               const float* __restrict__ wA, const float* __restrict__ wB,
               float* __restrict__ out)
{
    extern __shared__ float smem[];
    float* Tsm = smem;                    // [128][132]
    float* Sj = Tsm + BT * TPAD;          // [2][128][16]
    float* Si = Sj + 2 * BT * NOUT;       // [2][128][16]

    const int t = threadIdx.x;
    const int bi = blockIdx.y, bj = blockIdx.x;
    const int i0 = bi * BT, j0 = bj * BT;

    // stage S tiles for both groups (rows j-block for GEMM1, rows i-block for GEMM2)
    for (int idx = t; idx < 2 * BT * NOUT; idx += NTHREADS) {
        const int g = idx / (BT * NOUT);
        const int rem = idx - g * (BT * NOUT);
        const int r = rem >> 4;
        const int c = rem & 15;
        Sj[idx] = g_S[g][j0 + r][c];
        Si[idx] = g_S[g][i0 + r][c];
    }

    const bool fast = (i0 + BT <= NN_DIM) && (j0 + BT <= NN_DIM);

    unsigned long long accA[8], accB[8];
#pragma unroll
    for (int q = 0; q < 8; q++) { accA[q] = 0ull; accB[q] = 0ull; }

    do_group(A, 3, wA, Tsm, Sj, Si, i0, j0, t, fast, accA);
    do_group(At, 9, wB, Tsm, Sj + BT * NOUT, Si + BT * NOUT, i0, j0, t, fast, accB);

    // single atomic flush per thread
    const int grow = (t < BT) ? (i0 + t) : (j0 + (t - BT));
    if (grow < NN_DIM) {
        float* __restrict__ o = out + grow * 32;
#pragma unroll
        for (int q = 0; q < 8; q++) {
            const float2 a = unpack2(accA[q]);
            atomicAdd(o + 2 * q + 0, a.x);
            atomicAdd(o + 2 * q + 1, a.y);
            const float2 b = unpack2(accB[q]);
            atomicAdd(o + 16 + 2 * q + 0, b.x);
            atomicAdd(o + 16 + 2 * q + 1, b.y);
        }
    }
}

extern "C" void kernel_launch(void* const* d_in, const int* in_sizes, int n_in,
                              void* d_out, int out_size) {
    const float* feature = (const float*)d_in[0];  // [5000,128]
    const float* A       = (const float*)d_in[1];  // [3,5000,5000]
    const float* At      = (const float*)d_in[2];  // [9,5000,5000]
    const float* wb2     = (const float*)d_in[3];  // [3,1]
    const float* wb      = (const float*)d_in[4];  // [9,1]
    const float* W3      = (const float*)d_in[5];  // [128,16]
    const float* b3      = (const float*)d_in[6];  // [16]
    const float* W1      = (const float*)d_in[7];  // [128,16]
    const float* b1      = (const float*)d_in[8];  // [16]
    float* out = (float*)d_out;                    // [5000,32]

    // 1) S1/S2 + bias-init of out (out is poisoned 0xAA before timing)
    fame_prep<<<NN_DIM, 128>>>(feature, W3, b3, W1, b1, out);

    // 2) fused merged-adjacency x support, both groups, single pass over A/A_t
    const int smem_bytes = (BT * TPAD + 4 * BT * NOUT) * (int)sizeof(float);
    cudaFuncSetAttribute(fame_main, cudaFuncAttributeMaxDynamicSharedMemorySize, smem_bytes);
    dim3 grid((NN_DIM + BT - 1) / BT, (NN_DIM + BT - 1) / BT);
    fame_main<<<grid, NTHREADS, smem_bytes>>>(A, At, wb2, wb, out);
}

// round 3
// speedup vs baseline: 1.4520x; 1.4488x over previous
#include <cuda_runtime.h>
#include <cstdint>

#define NN_DIM 5000
#define NF 128
#define NOUT 16
#define NPAD 5120
#define BT 128
#define TPAD 132
#define NTHREADS 256

// S1 = feature@W3 (group 0), S2 = feature@W1 (group 1), padded rows are zero.
__device__ float g_S[2][NPAD][NOUT];

// ---------- packed f32x2 helpers ----------
__device__ __forceinline__ void fma2(unsigned long long &d, unsigned long long a,
                                     unsigned long long b) {
    asm("fma.rn.f32x2 %0, %1, %2, %0;" : "+l"(d) : "l"(a), "l"(b));
}
__device__ __forceinline__ unsigned long long pack2(float x) {
    unsigned long long r;
    asm("mov.b64 %0, {%1, %1};" : "=l"(r) : "f"(x));
    return r;
}
__device__ __forceinline__ float2 unpack2(unsigned long long v) {
    float2 f;
    asm("mov.b64 {%0, %1}, %2;" : "=f"(f.x), "=f"(f.y) : "l"(v));
    return f;
}
__device__ __forceinline__ void red_add_v4(float* p, float x, float y, float z, float w) {
    asm volatile("red.global.add.v4.f32 [%0], {%1, %2, %3, %4};"
                 :: "l"(p), "f"(x), "f"(y), "f"(z), "f"(w) : "memory");
}

// ---------------- prep: S1/S2 = feature @ W, bias-init out ----------------
__global__ void fame_prep(const float* __restrict__ feature,
                          const float* __restrict__ W3, const float* __restrict__ b3,
                          const float* __restrict__ W1, const float* __restrict__ b1,
                          float* __restrict__ out) {
    __shared__ float fsm[NF];
    const int row = blockIdx.x;
    const int t = threadIdx.x;
    fsm[t] = feature[row * NF + t];
    __syncthreads();
    if (t < 32) {
        const int g = t >> 4;
        const int c = t & 15;
        const float* __restrict__ W = g ? W1 : W3;
        float s = 0.f;
#pragma unroll 16
        for (int k = 0; k < NF; k++) s += fsm[k] * W[k * NOUT + c];
        g_S[g][row][c] = s;
    } else if (t < 64) {
        const int c = t - 32;
        out[row * 32 + c] = (c < 16) ? b3[c] : b1[c - 16];
    }
}

// --------------- one relation-group: stage S, loop matrices, flush ---------------
__device__ __forceinline__ void do_group(
    const float* __restrict__ mats, int nmat, const float* __restrict__ wv,
    float* __restrict__ Tsm, float* __restrict__ Sj, float* __restrict__ Si,
    int i0, int j0, int t, bool fast, int g, int goff, float* __restrict__ out)
{
    // protect S buffers from previous group's in-flight compute
    __syncthreads();

    // stage S for this group: Sj = rows j0.., Si = rows i0.. (128x16 each)
    for (int idx = t; idx < 2 * BT * NOUT; idx += NTHREADS) {
        const int half = idx / (BT * NOUT);
        const int rem = idx - half * (BT * NOUT);
        const int r = rem >> 4;
        const int c = rem & 15;
        if (half == 0) Sj[rem] = g_S[g][j0 + r][c];
        else           Si[rem] = g_S[g][i0 + r][c];
    }

    const int side = t >> 7;        // 0: direct (rows i), 1: transpose (rows j)
    const int tt = t & 127;
    const int l = tt & 31;          // lane within quad-group
    const int q = tt >> 5;          // which 32-wide k-range this thread covers

    unsigned long long acc[4][8];
#pragma unroll
    for (int a = 0; a < 4; a++)
#pragma unroll
        for (int b = 0; b < 8; b++) acc[a][b] = 0ull;

    for (int m = 0; m < nmat; m++) {
        const float* __restrict__ M = mats + (size_t)m * (size_t)NN_DIM * (size_t)NN_DIM;
        const float w = wv[m];

        __syncthreads();  // previous tile fully consumed (also orders S staging)

        // ---- stage 128x128 tile of M, pre-scaled by w ----
        if (fast) {
#pragma unroll
            for (int qq = 0; qq < 16; qq++) {
                const int idx = t + NTHREADS * qq;
                const int row = idx >> 5;
                const int c4 = idx & 31;
                const float4 v = *(const float4*)(M + (size_t)(i0 + row) * NN_DIM + (j0 + c4 * 4));
                float4 s;
                s.x = v.x * w; s.y = v.y * w; s.z = v.z * w; s.w = v.w * w;
                *(float4*)(Tsm + row * TPAD + c4 * 4) = s;
            }
        } else {
#pragma unroll
            for (int qq = 0; qq < 16; qq++) {
                const int idx = t + NTHREADS * qq;
                const int row = idx >> 5;
                const int c4 = idx & 31;
                const int gi = i0 + row;
                const int gj = j0 + c4 * 4;
                float4 s = make_float4(0.f, 0.f, 0.f, 0.f);
                if (gi < NN_DIM) {
                    const float* __restrict__ p = M + (size_t)gi * NN_DIM + gj;
                    if (gj + 3 < NN_DIM) {
                        const float4 v = *(const float4*)p;
                        s.x = v.x * w; s.y = v.y * w; s.z = v.z * w; s.w = v.w * w;
                    } else {
                        if (gj + 0 < NN_DIM) s.x = p[0] * w;
                        if (gj + 1 < NN_DIM) s.y = p[1] * w;
                        if (gj + 2 < NN_DIM) s.z = p[2] * w;
                    }
                }
                *(float4*)(Tsm + row * TPAD + c4 * 4) = s;
            }
        }
        __syncthreads();

        if (side == 0) {
            // GEMM1: acc[k][:] (rows l+32k) += sum_{j in [32q,32q+32)} T[row][j] * Sj[j,:]
            const int jbase = q * 32;
#pragma unroll 2
            for (int jc = 0; jc < 32; jc += 4) {
                const int j = jbase + jc;
                float4 Tv0 = *(const float4*)(Tsm + (l +  0) * TPAD + j);
                float4 Tv1 = *(const float4*)(Tsm + (l + 32) * TPAD + j);
                float4 Tv2 = *(const float4*)(Tsm + (l + 64) * TPAD + j);
                float4 Tv3 = *(const float4*)(Tsm + (l + 96) * TPAD + j);
#pragma unroll
                for (int jj = 0; jj < 4; jj++) {
                    const ulonglong2* __restrict__ Sp = (const ulonglong2*)(Sj + (j + jj) * NOUT);
                    const ulonglong2 s0 = Sp[0], s1 = Sp[1], s2 = Sp[2], s3 = Sp[3];
                    const float t0 = (jj == 0) ? Tv0.x : (jj == 1) ? Tv0.y : (jj == 2) ? Tv0.z : Tv0.w;
                    const float t1 = (jj == 0) ? Tv1.x : (jj == 1) ? Tv1.y : (jj == 2) ? Tv1.z : Tv1.w;
                    const float t2 = (jj == 0) ? Tv2.x : (jj == 1) ? Tv2.y : (jj == 2) ? Tv2.z : Tv2.w;
                    const float t3 = (jj == 0) ? Tv3.x : (jj == 1) ? Tv3.y : (jj == 2) ? Tv3.z : Tv3.w;
                    const unsigned long long m0 = pack2(t0), m1 = pack2(t1),
                                             m2 = pack2(t2), m3 = pack2(t3);
                    fma2(acc[0][0], m0, s0.x); fma2(acc[0][1], m0, s0.y);
                    fma2(acc[0][2], m0, s1.x); fma2(acc[0][3], m0, s1.y);
                    fma2(acc[0][4], m0, s2.x); fma2(acc[0][5], m0, s2.y);
                    fma2(acc[0][6], m0, s3.x); fma2(acc[0][7], m0, s3.y);
                    fma2(acc[1][0], m1, s0.x); fma2(acc[1][1], m1, s0.y);
                    fma2(acc[1][2], m1, s1.x); fma2(acc[1][3], m1, s1.y);
                    fma2(acc[1][4], m1, s2.x); fma2(acc[1][5], m1, s2.y);
                    fma2(acc[1][6], m1, s3.x); fma2(acc[1][7], m1, s3.y);
                    fma2(acc[2][0], m2, s0.x); fma2(acc[2][1], m2, s0.y);
                    fma2(acc[2][2], m2, s1.x); fma2(acc[2][3], m2, s1.y);
                    fma2(acc[2][4], m2, s2.x); fma2(acc[2][5], m2, s2.y);
                    fma2(acc[2][6], m2, s3.x); fma2(acc[2][7], m2, s3.y);
                    fma2(acc[3][0], m3, s0.x); fma2(acc[3][1], m3, s0.y);
                    fma2(acc[3][2], m3, s1.x); fma2(acc[3][3], m3, s1.y);
                    fma2(acc[3][4], m3, s2.x); fma2(acc[3][5], m3, s2.y);
                    fma2(acc[3][6], m3, s3.x); fma2(acc[3][7], m3, s3.y);
                }
            }
        } else {
            // GEMM2: acc[k][:] (cols 4l+k -> out rows j0+4l+k) += sum_{i in [32q,..)} T[i][4l+k] * Si[i,:]
            const int ibase = q * 32;
#pragma unroll 2
            for (int ii = 0; ii < 32; ii++) {
                const int i = ibase + ii;
                const float4 Tv = *(const float4*)(Tsm + i * TPAD + 4 * l);
                const ulonglong2* __restrict__ Sp = (const ulonglong2*)(Si + i * NOUT);
                const ulonglong2 s0 = Sp[0], s1 = Sp[1], s2 = Sp[2], s3 = Sp[3];
                const unsigned long long m0 = pack2(Tv.x), m1 = pack2(Tv.y),
                                         m2 = pack2(Tv.z), m3 = pack2(Tv.w);
                fma2(acc[0][0], m0, s0.x); fma2(acc[0][1], m0, s0.y);
                fma2(acc[0][2], m0, s1.x); fma2(acc[0][3], m0, s1.y);
                fma2(acc[0][4], m0, s2.x); fma2(acc[0][5], m0, s2.y);
                fma2(acc[0][6], m0, s3.x); fma2(acc[0][7], m0, s3.y);
                fma2(acc[1][0], m1, s0.x); fma2(acc[1][1], m1, s0.y);
                fma2(acc[1][2], m1, s1.x); fma2(acc[1][3], m1, s1.y);
                fma2(acc[1][4], m1, s2.x); fma2(acc[1][5], m1, s2.y);
                fma2(acc[1][6], m1, s3.x); fma2(acc[1][7], m1, s3.y);
                fma2(acc[2][0], m2, s0.x); fma2(acc[2][1], m2, s0.y);
                fma2(acc[2][2], m2, s1.x); fma2(acc[2][3], m2, s1.y);
                fma2(acc[2][4], m2, s2.x); fma2(acc[2][5], m2, s2.y);
                fma2(acc[2][6], m2, s3.x); fma2(acc[2][7], m2, s3.y);
                fma2(acc[3][0], m3, s0.x); fma2(acc[3][1], m3, s0.y);
                fma2(acc[3][2], m3, s1.x); fma2(acc[3][3], m3, s1.y);
                fma2(acc[3][4], m3, s2.x); fma2(acc[3][5], m3, s2.y);
                fma2(acc[3][6], m3, s3.x); fma2(acc[3][7], m3, s3.y);
            }
        }
    }

    // ---- flush: 128-bit vector reductions to out columns [goff, goff+16) ----
#pragma unroll
    for (int k = 0; k < 4; k++) {
        const int row = (side == 0) ? (i0 + l + 32 * k) : (j0 + 4 * l + k);
        if (row < NN_DIM) {
            float* __restrict__ o = out + (size_t)row * 32 + goff;
#pragma unroll
            for (int c = 0; c < 4; c++) {
                const float2 a = unpack2(acc[k][2 * c]);
                const float2 b = unpack2(acc[k][2 * c + 1]);
                red_add_v4(o + 4 * c, a.x, a.y, b.x, b.y);
            }
        }
    }
}

__global__ __launch_bounds__(NTHREADS, 2)
void fame_main(const float* __restrict__ A, const float* __restrict__ At,
               const float* __restrict__ wA, const float* __restrict__ wB,
               float* __restrict__ out)
{
    extern __shared__ float smem[];
    float* Tsm = smem;                    // [128][132]
    float* Sj = Tsm + BT * TPAD;          // [128][16]
    float* Si = Sj + BT * NOUT;           // [128][16]

    const int t = threadIdx.x;
    const int bi = blockIdx.y, bj = blockIdx.x;
    const int i0 = bi * BT, j0 = bj * BT;
    const bool fast = (i0 + BT <= NN_DIM) && (j0 + BT <= NN_DIM);

    do_group(A, 3, wA, Tsm, Sj, Si, i0, j0, t, fast, 0, 0, out);
    do_group(At, 9, wB, Tsm, Sj, Si, i0, j0, t, fast, 1, 16, out);
}

extern "C" void kernel_launch(void* const* d_in, const int* in_sizes, int n_in,
                              void* d_out, int out_size) {
    const float* feature = (const float*)d_in[0];  // [5000,128]
    const float* A       = (const float*)d_in[1];  // [3,5000,5000]
    const float* At      = (const float*)d_in[2];  // [9,5000,5000]
    const float* wb2     = (const float*)d_in[3];  // [3,1]
    const float* wb      = (const float*)d_in[4];  // [9,1]
    const float* W3      = (const float*)d_in[5];  // [128,16]
    const float* b3      = (const float*)d_in[6];  // [16]
    const float* W1      = (const float*)d_in[7];  // [128,16]
    const float* b1      = (const float*)d_in[8];  // [16]
    float* out = (float*)d_out;                    // [5000,32]

    fame_prep<<<NN_DIM, 128>>>(feature, W3, b3, W1, b1, out);

    const int smem_bytes = (BT * TPAD + 2 * BT * NOUT) * (int)sizeof(float);
    cudaFuncSetAttribute(fame_main, cudaFuncAttributeMaxDynamicSharedMemorySize, smem_bytes);
    dim3 grid((NN_DIM + BT - 1) / BT, (NN_DIM + BT - 1) / BT);
    fame_main<<<grid, NTHREADS, smem_bytes>>>(A, At, wb2, wb, out);
}